// round 4
// baseline (speedup 1.0000x reference)
#include <cuda_runtime.h>
#include <mma.h>
#include <cstdint>

using namespace nvcuda;

// Problem constants
#define E_EXPERTS 8
#define D_MODEL   1024
#define D_FF      4096
#define B_DIM     2
#define T_DIM     16384            // E * 2048
#define CAP       2048
#define M_TOTAL   (B_DIM * T_DIM)  // 32768

// Tiling
#define BM 128
#define BN 128
#define BK 32
#define A_LD 40     // 32 + pad (multiple of 4 for wmma ldm)
#define B_LD 136    // 128 + pad
#define SCR_LD 68   // epilogue scratch leading dim
#define NTHREADS 256

#define ASZ (BM * A_LD)   // 5120 floats
#define BSZ (BK * B_LD)   // 4352 floats
#define SMEM_FLOATS (2 * (ASZ + BSZ))
#define SMEM_BYTES  (SMEM_FLOATS * 4)   // 75776 bytes

// Intermediate H scratch: [32768, 4096] fp32 (536 MB) — static device global.
// Referenced directly from device code; no host-side symbol lookup needed.
__device__ float g_H[(size_t)M_TOTAL * D_FF];

__device__ __forceinline__ void cp16(float* s, const float* g) {
    uint32_t sa = (uint32_t)__cvta_generic_to_shared(s);
    asm volatile("cp.async.cg.shared.global [%0], [%1], 16;\n" :: "r"(sa), "l"(g));
}
__device__ __forceinline__ void cp_commit() {
    asm volatile("cp.async.commit_group;\n" ::: "memory");
}
__device__ __forceinline__ void cp_wait0() {
    asm volatile("cp.async.wait_group 0;\n" ::: "memory");
}

__device__ __forceinline__ float gelu_erf(float v) {
    return 0.5f * v * (1.0f + erff(v * 0.7071067811865475f));
}

// C[M,N] = act( A[M,K] @ W[e][K,N] + bias[e][N] )
// A row-major, W per-expert row-major [K, N]. Each 128-row M-tile maps to a
// single expert: e = (m0 mod T_DIM) / CAP.
// GH_IN:  read A from g_H (ignore Ain).  GH_OUT: write result to g_H.
template <bool GELU, bool GH_IN, bool GH_OUT>
__global__ void __launch_bounds__(NTHREADS, 2)
ffn_gemm(const float* __restrict__ Ain, const float* __restrict__ W,
         const float* __restrict__ bias, float* __restrict__ OutArg,
         int K, int N)
{
    extern __shared__ float smem[];
    float* As0 = smem;
    float* Bs0 = smem + ASZ;
    float* As1 = smem + ASZ + BSZ;
    float* Bs1 = smem + ASZ + BSZ + ASZ;
    float* AsBuf[2] = {As0, As1};
    float* BsBuf[2] = {Bs0, Bs1};

    const float* A  = GH_IN  ? (const float*)g_H : Ain;
    float*       Out = GH_OUT ? g_H : OutArg;

    const int tid  = threadIdx.x;
    const int warp = tid >> 5;
    const int lane = tid & 31;
    const int warpM = warp >> 1;   // 0..3 (rows of 32)
    const int warpN = warp & 1;    // 0..1 (cols of 64)

    const int n0 = blockIdx.x * BN;
    const int m0 = blockIdx.y * BM;
    const int e  = (m0 & (T_DIM - 1)) >> 11;   // expert for this whole tile

    const float* Abase = A + (size_t)m0 * K;
    const float* Wbase = W + (size_t)e * K * N + n0;
    const float* bptr  = bias + (size_t)e * N + n0;

    // ---- tile loaders (cp.async, 16B each) ----
    // A tile: BM x BK. 256 threads * float4 = 1024 elems/pass, 4 passes.
    const int ar  = tid >> 3;          // 0..31
    const int ac4 = (tid & 7) << 2;    // 0,4,...,28
    // B tile: BK x BN. row = tid/32 (0..7), col4 = (tid%32)*4, 4 passes.
    const int br  = tid >> 5;          // 0..7
    const int bc4 = (tid & 31) << 2;   // 0..124

    auto load_tile = [&](int kt, float* Ad, float* Bd) {
        const float* As_g = Abase + (size_t)kt * BK;
        #pragma unroll
        for (int i = 0; i < 4; i++) {
            int row = ar + i * 32;
            cp16(Ad + row * A_LD + ac4, As_g + (size_t)row * K + ac4);
        }
        const float* Bs_g = Wbase + (size_t)kt * BK * N;
        #pragma unroll
        for (int i = 0; i < 4; i++) {
            int row = br + i * 8;
            cp16(Bd + row * B_LD + bc4, Bs_g + (size_t)row * N + bc4);
        }
    };

    // ---- accumulators ----
    wmma::fragment<wmma::accumulator, 16, 16, 8, float> c[2][4];
    #pragma unroll
    for (int mi = 0; mi < 2; mi++)
        #pragma unroll
        for (int ni = 0; ni < 4; ni++)
            wmma::fill_fragment(c[mi][ni], 0.0f);

    const int KT = K / BK;

    load_tile(0, AsBuf[0], BsBuf[0]);
    cp_commit();
    cp_wait0();
    __syncthreads();

    for (int kt = 0; kt < KT; ++kt) {
        const int cur = kt & 1;
        if (kt + 1 < KT) {
            load_tile(kt + 1, AsBuf[cur ^ 1], BsBuf[cur ^ 1]);
            cp_commit();
        }
        float* As = AsBuf[cur];
        float* Bs = BsBuf[cur];

        #pragma unroll
        for (int ks = 0; ks < 4; ks++) {
            wmma::fragment<wmma::matrix_a, 16, 16, 8, wmma::precision::tf32,
                           wmma::row_major> a[2];
            wmma::fragment<wmma::matrix_b, 16, 16, 8, wmma::precision::tf32,
                           wmma::row_major> b[4];
            #pragma unroll
            for (int mi = 0; mi < 2; mi++) {
                wmma::load_matrix_sync(
                    a[mi], As + (warpM * 32 + mi * 16) * A_LD + ks * 8, A_LD);
                #pragma unroll
                for (int t = 0; t < a[mi].num_elements; t++)
                    a[mi].x[t] = wmma::__float_to_tf32(a[mi].x[t]);
            }
            #pragma unroll
            for (int ni = 0; ni < 4; ni++) {
                wmma::load_matrix_sync(
                    b[ni], Bs + (ks * 8) * B_LD + warpN * 64 + ni * 16, B_LD);
                #pragma unroll
                for (int t = 0; t < b[ni].num_elements; t++)
                    b[ni].x[t] = wmma::__float_to_tf32(b[ni].x[t]);
            }
            #pragma unroll
            for (int mi = 0; mi < 2; mi++)
                #pragma unroll
                for (int ni = 0; ni < 4; ni++)
                    wmma::mma_sync(c[mi][ni], a[mi], b[ni], c[mi][ni]);
        }

        if (kt + 1 < KT) cp_wait0();
        __syncthreads();
    }

    // ---- epilogue: per-warp smem scratch (reuse tile smem), bias + act ----
    float* scr = smem + warp * (32 * SCR_LD);
    #pragma unroll
    for (int mi = 0; mi < 2; mi++)
        #pragma unroll
        for (int ni = 0; ni < 4; ni++)
            wmma::store_matrix_sync(scr + (mi * 16) * SCR_LD + ni * 16,
                                    c[mi][ni], SCR_LD, wmma::mem_row_major);
    __syncwarp();

    const int rowBase = m0 + warpM * 32;
    const int colBase = warpN * 64;       // within the BN tile
    #pragma unroll 4
    for (int i = lane; i < 32 * 64; i += 32) {
        int r = i >> 6;
        int cc = i & 63;
        float v = scr[r * SCR_LD + cc] + bptr[colBase + cc];
        if (GELU) v = gelu_erf(v);
        Out[(size_t)(rowBase + r) * N + n0 + colBase + cc] = v;
    }
}

extern "C" void kernel_launch(void* const* d_in, const int* in_sizes, int n_in,
                              void* d_out, int out_size)
{
    (void)in_sizes; (void)n_in; (void)out_size;
    const float* x  = (const float*)d_in[0];
    const float* w1 = (const float*)d_in[1];
    const float* b1 = (const float*)d_in[2];
    const float* w2 = (const float*)d_in[3];
    const float* b2 = (const float*)d_in[4];
    float* out = (float*)d_out;

    static bool attr_done = false;
    if (!attr_done) {
        cudaFuncSetAttribute(ffn_gemm<true, false, true>,
                             cudaFuncAttributeMaxDynamicSharedMemorySize, SMEM_BYTES);
        cudaFuncSetAttribute(ffn_gemm<false, true, false>,
                             cudaFuncAttributeMaxDynamicSharedMemorySize, SMEM_BYTES);
        attr_done = true;
    }

    dim3 block(NTHREADS);
    // GEMM1: x[32768,1024] @ w1[e][1024,4096] + b1, GELU -> g_H
    dim3 grid1(D_FF / BN, M_TOTAL / BM);
    ffn_gemm<true, false, true><<<grid1, block, SMEM_BYTES>>>(
        x, w1, b1, nullptr, D_MODEL, D_FF);
    // GEMM2: g_H[32768,4096] @ w2[e][4096,1024] + b2 -> out
    dim3 grid2(D_MODEL / BN, M_TOTAL / BM);
    ffn_gemm<false, true, false><<<grid2, block, SMEM_BYTES>>>(
        nullptr, w2, b2, out, D_FF, D_MODEL);
}

// round 7
// speedup vs baseline: 2.1287x; 2.1287x over previous
#include <cuda_runtime.h>
#include <cstdint>
#include <math.h>

// ---------------- problem constants ----------------
#define E_EXPERTS 8
#define D_MODEL   1024
#define D_FF      4096
#define T_DIM     16384            // E * 2048
#define M_TOTAL   32768            // B * T

// ---------------- tiling ----------------
#define BM 128
#define BN 128
#define BK 32
#define STAGES 3
#define NTHREADS 256

#define A_LD 36                     // 32 + 4 pad (conflict-free frag loads)
#define B_LD 136                    // 128 + 8 pad
#define A_STG (BM * A_LD)           // 4608 floats
#define B_STG (BK * B_LD)           // 4352 floats
#define STG_FLOATS (A_STG + B_STG)  // 8960 floats
#define SMEM_BYTES (STAGES * STG_FLOATS * 4)   // 107520 B -> 2 CTAs/SM

// ---------------- device scratch ----------------
__device__ float g_H  [(size_t)M_TOTAL * D_FF];              // 536 MB
__device__ float g_XR [(size_t)M_TOTAL * D_MODEL];           // tf32-rounded x
__device__ float g_W1R[(size_t)E_EXPERTS * D_MODEL * D_FF];  // tf32-rounded w1
__device__ float g_W2R[(size_t)E_EXPERTS * D_FF * D_MODEL];  // tf32-rounded w2

// ---------------- helpers ----------------
__device__ __forceinline__ uint32_t smem_u32(const void* p) {
    uint32_t a;
    asm("{ .reg .u64 t; cvta.to.shared.u64 t, %1; cvt.u32.u64 %0, t; }"
        : "=r"(a) : "l"(p));
    return a;
}
__device__ __forceinline__ void cp16(uint32_t s, const float* g) {
    asm volatile("cp.async.cg.shared.global [%0], [%1], 16;\n" :: "r"(s), "l"(g));
}
__device__ __forceinline__ void cp_commit() {
    asm volatile("cp.async.commit_group;\n" ::: "memory");
}
__device__ __forceinline__ void cp_wait1() {
    asm volatile("cp.async.wait_group 1;\n" ::: "memory");
}

__device__ __forceinline__ float tf32rn(float v) {
    uint32_t o;
    asm("cvt.rna.tf32.f32 %0, %1;" : "=r"(o) : "f"(v));
    return __uint_as_float(o);
}
__device__ __forceinline__ float gelu_erf(float v) {
    return 0.5f * v * (1.0f + erff(v * 0.7071067811865475f));
}

__device__ __forceinline__ void mma_tf32(float* c, const uint32_t* a,
                                         const uint32_t* b) {
    asm volatile(
        "mma.sync.aligned.m16n8k8.row.col.f32.tf32.tf32.f32 "
        "{%0,%1,%2,%3}, {%4,%5,%6,%7}, {%8,%9}, {%0,%1,%2,%3};"
        : "+f"(c[0]), "+f"(c[1]), "+f"(c[2]), "+f"(c[3])
        : "r"(a[0]), "r"(a[1]), "r"(a[2]), "r"(a[3]), "r"(b[0]), "r"(b[1]));
}

// ---------------- tf32 pre-round pass ----------------
// DSEL: 0 -> g_XR, 1 -> g_W1R, 2 -> g_W2R
template <int DSEL>
__global__ void round_tf32(const float* __restrict__ src, size_t n4) {
    float* dst = (DSEL == 0) ? g_XR : (DSEL == 1) ? g_W1R : g_W2R;
    const float4* s = (const float4*)src;
    float4* d = (float4*)dst;
    for (size_t i = (size_t)blockIdx.x * blockDim.x + threadIdx.x; i < n4;
         i += (size_t)gridDim.x * blockDim.x) {
        float4 v = s[i];
        v.x = tf32rn(v.x); v.y = tf32rn(v.y);
        v.z = tf32rn(v.z); v.w = tf32rn(v.w);
        d[i] = v;
    }
}

// ---------------- main mma.sync tf32 GEMM ----------------
// Out[m, n] = act( sum_k A[m,k] * W[e][k,n] + bias[e][n] )
// A: ASEL 0 -> g_XR [M,1024], 1 -> g_H [M,4096] (both tf32-rounded)
// W: WSEL 1 -> g_W1R [E][1024][4096], 2 -> g_W2R [E][4096][1024] (row-major K x N)
template <bool GELU, int ASEL, int WSEL, bool OUT_H>
__global__ void __launch_bounds__(NTHREADS, 2)
ffn_mma(const float* __restrict__ bias, float* __restrict__ OutExt,
        int K, int Ntot)
{
    extern __shared__ float sm[];

    const int tid   = threadIdx.x;
    const int warp  = tid >> 5;
    const int lane  = tid & 31;
    const int warpM = warp >> 2;      // 0..1 : 64-row bands
    const int warpN = warp & 3;       // 0..3 : 32-col bands
    const int gq    = lane >> 2;      // 0..7
    const int lr    = lane & 3;       // 0..3

    const int n0 = blockIdx.x * BN;
    const int m0 = blockIdx.y * BM;
    const int e  = (m0 & (T_DIM - 1)) >> 11;

    const float* A = (ASEL == 0) ? g_XR : g_H;
    const float* W = (WSEL == 1) ? g_W1R : g_W2R;
    float* Out = OUT_H ? g_H : OutExt;

    const float* Abase = A + (size_t)m0 * K;
    const float* Wbase = W + (size_t)e * ((size_t)K * Ntot) + n0;

    // ---- stage loader (cp.async): A 128x32, B 32x128 ----
    auto load_stage = [&](int kt, int s) {
        float* Ad = sm + s * STG_FLOATS;
        float* Bd = Ad + A_STG;
        const float* Ag = Abase + (size_t)kt * BK;
        #pragma unroll
        for (int i = 0; i < 4; i++) {
            int cid = tid + i * NTHREADS;
            int row = cid >> 3, c4 = (cid & 7) << 2;
            cp16(smem_u32(Ad + row * A_LD + c4), Ag + (size_t)row * K + c4);
        }
        const float* Bg = Wbase + (size_t)(kt * BK) * Ntot;
        #pragma unroll
        for (int i = 0; i < 4; i++) {
            int cid = tid + i * NTHREADS;
            int row = cid >> 5, c4 = (cid & 31) << 2;
            cp16(smem_u32(Bd + row * B_LD + c4), Bg + (size_t)row * Ntot + c4);
        }
    };

    // ---- accumulators: warp tile 64x32 = 4 m-frags x 4 n-frags ----
    float acc[4][4][4];
    #pragma unroll
    for (int mi = 0; mi < 4; mi++)
        #pragma unroll
        for (int ni = 0; ni < 4; ni++)
            #pragma unroll
            for (int t = 0; t < 4; t++)
                acc[mi][ni][t] = 0.0f;

    const int KT = K / BK;

    load_stage(0, 0); cp_commit();
    load_stage(1, 1); cp_commit();

    const int aRow0 = warpM * 64 + gq;
    const int bCol0 = warpN * 32 + gq;

    for (int kt = 0; kt < KT; ++kt) {
        cp_wait1();              // stage kt resident (one group always newer)
        __syncthreads();         // all warps done reading stage kt-1

        if (kt + 2 < KT) load_stage(kt + 2, (kt + 2) % STAGES);
        cp_commit();             // always commit: uniform group accounting

        const uint32_t* As = (const uint32_t*)(sm + (kt % STAGES) * STG_FLOATS);
        const uint32_t* Bs = As + A_STG;

        #pragma unroll
        for (int ks = 0; ks < 4; ks++) {
            const int kc = ks * 8 + lr;
            uint32_t a[4][4];
            #pragma unroll
            for (int mi = 0; mi < 4; mi++) {
                int r = aRow0 + mi * 16;
                a[mi][0] = As[r * A_LD + kc];
                a[mi][1] = As[(r + 8) * A_LD + kc];
                a[mi][2] = As[r * A_LD + kc + 4];
                a[mi][3] = As[(r + 8) * A_LD + kc + 4];
            }
            uint32_t b[4][2];
            #pragma unroll
            for (int ni = 0; ni < 4; ni++) {
                int nn = bCol0 + ni * 8;
                b[ni][0] = Bs[kc * B_LD + nn];
                b[ni][1] = Bs[(kc + 4) * B_LD + nn];
            }
            #pragma unroll
            for (int mi = 0; mi < 4; mi++)
                #pragma unroll
                for (int ni = 0; ni < 4; ni++)
                    mma_tf32(acc[mi][ni], a[mi], b[ni]);
        }
    }

    // ---- epilogue: direct STG, bias + optional erf-GELU ----
    const float* bptr = bias + (size_t)e * Ntot;
    #pragma unroll
    for (int mi = 0; mi < 4; mi++) {
        int r = m0 + warpM * 64 + mi * 16 + gq;
        #pragma unroll
        for (int ni = 0; ni < 4; ni++) {
            int col = n0 + warpN * 32 + ni * 8 + lr * 2;
            float bb0 = __ldg(bptr + col);
            float bb1 = __ldg(bptr + col + 1);
            float v0 = acc[mi][ni][0] + bb0;
            float v1 = acc[mi][ni][1] + bb1;
            float v2 = acc[mi][ni][2] + bb0;
            float v3 = acc[mi][ni][3] + bb1;
            if (GELU) {
                v0 = gelu_erf(v0); v1 = gelu_erf(v1);
                v2 = gelu_erf(v2); v3 = gelu_erf(v3);
            }
            if (OUT_H) {         // feeds GEMM2's A: pre-round to tf32
                v0 = tf32rn(v0); v1 = tf32rn(v1);
                v2 = tf32rn(v2); v3 = tf32rn(v3);
            }
            float2 p0 = make_float2(v0, v1);
            float2 p1 = make_float2(v2, v3);
            *(float2*)&Out[(size_t)r * Ntot + col] = p0;
            *(float2*)&Out[(size_t)(r + 8) * Ntot + col] = p1;
        }
    }
}

// ---------------- host launcher ----------------
extern "C" void kernel_launch(void* const* d_in, const int* in_sizes, int n_in,
                              void* d_out, int out_size)
{
    (void)in_sizes; (void)n_in; (void)out_size;
    const float* x  = (const float*)d_in[0];
    const float* w1 = (const float*)d_in[1];
    const float* b1 = (const float*)d_in[2];
    const float* w2 = (const float*)d_in[3];
    const float* b2 = (const float*)d_in[4];
    float* out = (float*)d_out;

    cudaFuncSetAttribute(ffn_mma<true, 0, 1, true>,
                         cudaFuncAttributeMaxDynamicSharedMemorySize, SMEM_BYTES);
    cudaFuncSetAttribute(ffn_mma<false, 1, 2, false>,
                         cudaFuncAttributeMaxDynamicSharedMemorySize, SMEM_BYTES);

    // tf32 pre-round: x, w1, w2  (float4 grid-stride)
    const size_t nx4 = (size_t)M_TOTAL * D_MODEL / 4;                 // 8.39M
    const size_t nw4 = (size_t)E_EXPERTS * D_MODEL * D_FF / 4;        // 8.39M
    round_tf32<0><<<16384, 256>>>(x,  nx4);
    round_tf32<1><<<16384, 256>>>(w1, nw4);
    round_tf32<2><<<16384, 256>>>(w2, nw4);

    // GEMM1: g_XR [32768,1024] @ w1 -> bias + gelu -> g_H [32768,4096] (tf32)
    ffn_mma<true, 0, 1, true>
        <<<dim3(D_FF / BN, M_TOTAL / BM), NTHREADS, SMEM_BYTES>>>(
            b1, nullptr, D_MODEL, D_FF);
    // GEMM2: g_H [32768,4096] @ w2 + b2 -> out [32768,1024]
    ffn_mma<false, 1, 2, false>
        <<<dim3(D_MODEL / BN, M_TOTAL / BM), NTHREADS, SMEM_BYTES>>>(
            b2, out, D_FF, D_MODEL);
}

// round 8
// speedup vs baseline: 2.1474x; 1.0088x over previous
#include <cuda_runtime.h>
#include <cstdint>
#include <math.h>

// ---------------- problem constants ----------------
#define E_EXPERTS 8
#define D_MODEL   1024
#define D_FF      4096
#define T_DIM     16384            // E * 2048
#define M_TOTAL   32768            // B * T

// ---------------- tiling ----------------
#define BM 128
#define BN 256
#define BK 32
#define STAGES 3
#define NTHREADS 256

#define A_LD 36                     // 32 + 4 pad (conflict-free frag loads)
#define B_LD 264                    // 256 + 8 pad
#define A_STG (BM * A_LD)           // 4608 floats
#define B_STG (BK * B_LD)           // 8448 floats
#define STG_FLOATS (A_STG + B_STG)  // 13056 floats
#define SMEM_BYTES (STAGES * STG_FLOATS * 4)   // 156672 B -> 1 CTA/SM

// ---------------- device scratch ----------------
__device__ float g_H  [(size_t)M_TOTAL * D_FF];              // 536 MB
__device__ float g_XR [(size_t)M_TOTAL * D_MODEL];           // tf32-rounded x
__device__ float g_W1R[(size_t)E_EXPERTS * D_MODEL * D_FF];  // tf32-rounded w1
__device__ float g_W2R[(size_t)E_EXPERTS * D_FF * D_MODEL];  // tf32-rounded w2

// ---------------- helpers ----------------
__device__ __forceinline__ uint32_t smem_u32(const void* p) {
    uint32_t a;
    asm("{ .reg .u64 t; cvta.to.shared.u64 t, %1; cvt.u32.u64 %0, t; }"
        : "=r"(a) : "l"(p));
    return a;
}
__device__ __forceinline__ void cp16(uint32_t s, const float* g) {
    asm volatile("cp.async.cg.shared.global [%0], [%1], 16;\n" :: "r"(s), "l"(g));
}
__device__ __forceinline__ void cp_commit() {
    asm volatile("cp.async.commit_group;\n" ::: "memory");
}
__device__ __forceinline__ void cp_wait1() {
    asm volatile("cp.async.wait_group 1;\n" ::: "memory");
}

__device__ __forceinline__ float tf32rn(float v) {
    uint32_t o;
    asm("cvt.rna.tf32.f32 %0, %1;" : "=r"(o) : "f"(v));
    return __uint_as_float(o);
}
__device__ __forceinline__ float gelu_erf(float v) {
    return 0.5f * v * (1.0f + erff(v * 0.7071067811865475f));
}

__device__ __forceinline__ void mma_tf32(float* c, const uint32_t* a,
                                         const uint32_t* b) {
    asm volatile(
        "mma.sync.aligned.m16n8k8.row.col.f32.tf32.tf32.f32 "
        "{%0,%1,%2,%3}, {%4,%5,%6,%7}, {%8,%9}, {%0,%1,%2,%3};"
        : "+f"(c[0]), "+f"(c[1]), "+f"(c[2]), "+f"(c[3])
        : "r"(a[0]), "r"(a[1]), "r"(a[2]), "r"(a[3]), "r"(b[0]), "r"(b[1]));
}

// ---------------- tf32 pre-round pass ----------------
// DSEL: 0 -> g_XR, 1 -> g_W1R, 2 -> g_W2R
template <int DSEL>
__global__ void round_tf32(const float* __restrict__ src, size_t n4) {
    float* dst = (DSEL == 0) ? g_XR : (DSEL == 1) ? g_W1R : g_W2R;
    const float4* s = (const float4*)src;
    float4* d = (float4*)dst;
    for (size_t i = (size_t)blockIdx.x * blockDim.x + threadIdx.x; i < n4;
         i += (size_t)gridDim.x * blockDim.x) {
        float4 v = s[i];
        v.x = tf32rn(v.x); v.y = tf32rn(v.y);
        v.z = tf32rn(v.z); v.w = tf32rn(v.w);
        d[i] = v;
    }
}

// ---------------- main mma.sync tf32 GEMM ----------------
// Out[m, n] = act( sum_k A[m,k] * W[e][k,n] + bias[e][n] )
// CTA tile 128x256, warp tile 64x64 (8 warps: 2 M-bands x 4 N-bands).
// A: ASEL 0 -> g_XR [M,1024], 1 -> g_H [M,4096] (both tf32-rounded)
// W: WSEL 1 -> g_W1R [E][1024][4096], 2 -> g_W2R [E][4096][1024] (row-major K x N)
template <bool GELU, int ASEL, int WSEL, bool OUT_H>
__global__ void __launch_bounds__(NTHREADS, 1)
ffn_mma(const float* __restrict__ bias, float* __restrict__ OutExt,
        int K, int Ntot)
{
    extern __shared__ float sm[];

    const int tid   = threadIdx.x;
    const int warp  = tid >> 5;
    const int lane  = tid & 31;
    const int warpM = warp >> 2;      // 0..1 : 64-row bands
    const int warpN = warp & 3;       // 0..3 : 64-col bands
    const int gq    = lane >> 2;      // 0..7
    const int lr    = lane & 3;       // 0..3

    const int n0 = blockIdx.x * BN;
    const int m0 = blockIdx.y * BM;
    const int e  = (m0 & (T_DIM - 1)) >> 11;

    const float* A = (ASEL == 0) ? g_XR : g_H;
    const float* W = (WSEL == 1) ? g_W1R : g_W2R;
    float* Out = OUT_H ? g_H : OutExt;

    const float* Abase = A + (size_t)m0 * K;
    const float* Wbase = W + (size_t)e * ((size_t)K * Ntot) + n0;

    // ---- stage loader (cp.async): A 128x32, B 32x256 ----
    auto load_stage = [&](int kt, int s) {
        float* Ad = sm + s * STG_FLOATS;
        float* Bd = Ad + A_STG;
        const float* Ag = Abase + (size_t)kt * BK;
        #pragma unroll
        for (int i = 0; i < 4; i++) {
            int cid = tid + i * NTHREADS;
            int row = cid >> 3, c4 = (cid & 7) << 2;
            cp16(smem_u32(Ad + row * A_LD + c4), Ag + (size_t)row * K + c4);
        }
        const float* Bg = Wbase + (size_t)(kt * BK) * Ntot;
        #pragma unroll
        for (int i = 0; i < 8; i++) {
            int cid = tid + i * NTHREADS;
            int row = cid >> 6, c4 = (cid & 63) << 2;
            cp16(smem_u32(Bd + row * B_LD + c4), Bg + (size_t)row * Ntot + c4);
        }
    };

    // ---- accumulators: warp tile 64x64 = 4 m-frags x 8 n-frags ----
    float acc[4][8][4];
    #pragma unroll
    for (int mi = 0; mi < 4; mi++)
        #pragma unroll
        for (int ni = 0; ni < 8; ni++)
            #pragma unroll
            for (int t = 0; t < 4; t++)
                acc[mi][ni][t] = 0.0f;

    const int KT = K / BK;

    load_stage(0, 0); cp_commit();
    load_stage(1, 1); cp_commit();

    const int aRow0 = warpM * 64 + gq;
    const int bCol0 = warpN * 64 + gq;

    for (int kt = 0; kt < KT; ++kt) {
        cp_wait1();              // stage kt resident (one group always newer)
        __syncthreads();         // all warps done reading stage kt-1

        if (kt + 2 < KT) load_stage(kt + 2, (kt + 2) % STAGES);
        cp_commit();             // always commit: uniform group accounting

        const uint32_t* As = (const uint32_t*)(sm + (kt % STAGES) * STG_FLOATS);
        const uint32_t* Bs = As + A_STG;

        #pragma unroll
        for (int ks = 0; ks < 4; ks++) {
            const int kc = ks * 8 + lr;
            uint32_t a[4][4];
            #pragma unroll
            for (int mi = 0; mi < 4; mi++) {
                int r = aRow0 + mi * 16;
                a[mi][0] = As[r * A_LD + kc];
                a[mi][1] = As[(r + 8) * A_LD + kc];
                a[mi][2] = As[r * A_LD + kc + 4];
                a[mi][3] = As[(r + 8) * A_LD + kc + 4];
            }
            uint32_t b[8][2];
            #pragma unroll
            for (int ni = 0; ni < 8; ni++) {
                int nn = bCol0 + ni * 8;
                b[ni][0] = Bs[kc * B_LD + nn];
                b[ni][1] = Bs[(kc + 4) * B_LD + nn];
            }
            #pragma unroll
            for (int mi = 0; mi < 4; mi++)
                #pragma unroll
                for (int ni = 0; ni < 8; ni++)
                    mma_tf32(acc[mi][ni], a[mi], b[ni]);
        }
    }

    // ---- epilogue: direct STG, bias + optional erf-GELU ----
    const float* bptr = bias + (size_t)e * Ntot;
    float bb0[8], bb1[8];
    #pragma unroll
    for (int ni = 0; ni < 8; ni++) {
        int col = n0 + warpN * 64 + ni * 8 + lr * 2;
        bb0[ni] = __ldg(bptr + col);
        bb1[ni] = __ldg(bptr + col + 1);
    }
    #pragma unroll
    for (int mi = 0; mi < 4; mi++) {
        int r = m0 + warpM * 64 + mi * 16 + gq;
        #pragma unroll
        for (int ni = 0; ni < 8; ni++) {
            int col = n0 + warpN * 64 + ni * 8 + lr * 2;
            float v0 = acc[mi][ni][0] + bb0[ni];
            float v1 = acc[mi][ni][1] + bb1[ni];
            float v2 = acc[mi][ni][2] + bb0[ni];
            float v3 = acc[mi][ni][3] + bb1[ni];
            if (GELU) {
                v0 = gelu_erf(v0); v1 = gelu_erf(v1);
                v2 = gelu_erf(v2); v3 = gelu_erf(v3);
            }
            if (OUT_H) {         // feeds GEMM2's A: pre-round to tf32
                v0 = tf32rn(v0); v1 = tf32rn(v1);
                v2 = tf32rn(v2); v3 = tf32rn(v3);
            }
            float2 p0 = make_float2(v0, v1);
            float2 p1 = make_float2(v2, v3);
            *(float2*)&Out[(size_t)r * Ntot + col] = p0;
            *(float2*)&Out[(size_t)(r + 8) * Ntot + col] = p1;
        }
    }
}

// ---------------- host launcher ----------------
extern "C" void kernel_launch(void* const* d_in, const int* in_sizes, int n_in,
                              void* d_out, int out_size)
{
    (void)in_sizes; (void)n_in; (void)out_size;
    const float* x  = (const float*)d_in[0];
    const float* w1 = (const float*)d_in[1];
    const float* b1 = (const float*)d_in[2];
    const float* w2 = (const float*)d_in[3];
    const float* b2 = (const float*)d_in[4];
    float* out = (float*)d_out;

    cudaFuncSetAttribute(ffn_mma<true, 0, 1, true>,
                         cudaFuncAttributeMaxDynamicSharedMemorySize, SMEM_BYTES);
    cudaFuncSetAttribute(ffn_mma<false, 1, 2, false>,
                         cudaFuncAttributeMaxDynamicSharedMemorySize, SMEM_BYTES);

    // tf32 pre-round: x, w1, w2  (float4 grid-stride)
    const size_t nx4 = (size_t)M_TOTAL * D_MODEL / 4;                 // 8.39M
    const size_t nw4 = (size_t)E_EXPERTS * D_MODEL * D_FF / 4;        // 8.39M
    round_tf32<0><<<16384, 256>>>(x,  nx4);
    round_tf32<1><<<16384, 256>>>(w1, nw4);
    round_tf32<2><<<16384, 256>>>(w2, nw4);

    // GEMM1: g_XR [32768,1024] @ w1 -> bias + gelu -> g_H [32768,4096] (tf32)
    ffn_mma<true, 0, 1, true>
        <<<dim3(D_FF / BN, M_TOTAL / BM), NTHREADS, SMEM_BYTES>>>(
            b1, nullptr, D_MODEL, D_FF);
    // GEMM2: g_H [32768,4096] @ w2 + b2 -> out [32768,1024]
    ffn_mma<false, 1, 2, false>
        <<<dim3(D_MODEL / BN, M_TOTAL / BM), NTHREADS, SMEM_BYTES>>>(
            b2, out, D_FF, D_MODEL);
}